// round 15
// baseline (speedup 1.0000x reference)
#include <cuda_runtime.h>
#include <cuda_bf16.h>

#define NN 5200    // nodes
#define NI 5200    // incidences
#define NH 1000    // hyperedges
#define ND 4096    // feature dim
#define NEG 0.01f
#define ESL 48     // slots per edge bin (max degree seed-0 ~17, Poisson(5.2))
#define NSL 16     // slots per node bin (max degree ~9, Poisson(1))
#define NCHUNK 4   // 4 x 1024 floats = full 4096 row per block
#define NPB 4      // nodes per block in k_node

// ---------------- device scratch (no allocations; zero-init at load) ----------------
__device__ int   g_ncur[NN];          // node cursors -> final counts
__device__ int   g_ecur[NH];          // edge cursors -> final counts
__device__ float g_D[NN];
__device__ float g_B[NH];
__device__ int   g_ell_n[NN * NSL];   // per-node list of edge ids (padded)
__device__ int   g_ell_e[NH * ESL];   // per-edge list of node ids (padded)

// ---------------- K0: zero cursors + accumulators ----------------
__global__ void k_zero() {
    int i = blockIdx.x * blockDim.x + threadIdx.x;
    if (i < NN) { g_ncur[i] = 0; g_D[i] = 0.f; }
    if (i < NH) { g_ecur[i] = 0; g_B[i] = 0.f; }
}

// ---------------- K1: build ELL + degree sums via chip-wide global atomics ----------------
__global__ void k_build(const int* __restrict__ node_idx,
                        const int* __restrict__ edge_idx,
                        const float* __restrict__ hw,
                        const float* __restrict__ ew) {
    int i = blockIdx.x * blockDim.x + threadIdx.x;
    if (i >= NI) return;
    int n = node_idx[i];
    int e = edge_idx[i];
    int p = atomicAdd(&g_ecur[e], 1);
    if (p < ESL) g_ell_e[e * ESL + p] = n;   // fire-and-forget STG
    int q = atomicAdd(&g_ncur[n], 1);
    if (q < NSL) g_ell_n[n * NSL + q] = e;   // fire-and-forget STG
    atomicAdd(&g_D[n], hw[e]);               // REDG, no return
    atomicAdd(&g_B[e], ew[n]);               // REDG, no return
}

// ---------------- K2: edge aggregation (one block per hyperedge) ----------------
// grid: NH, block: 256 threads, 4 float4 chunks; first 8 ELL indices hoisted
__global__ void __launch_bounds__(256) k_edge(const float* __restrict__ feat,
                                              float* __restrict__ out_edge) {
    int e  = blockIdx.x;
    int d0 = threadIdx.x * 4;
    int cnt = g_ecur[e]; cnt = cnt < ESL ? cnt : ESL;
    float bsum = g_B[e];
    float b = (bsum == 0.f) ? 0.f : 1.f / bsum;
    const int4* row4 = reinterpret_cast<const int4*>(g_ell_e + e * ESL);
    // hoist first 8 indices (covers ~92% of edges fully)
    int4 r0 = row4[0];
    int4 r1 = row4[1];
    int ridx[8] = {r0.x, r0.y, r0.z, r0.w, r1.x, r1.y, r1.z, r1.w};

    float4 acc[NCHUNK];
#pragma unroll
    for (int c = 0; c < NCHUNK; c++) acc[c] = make_float4(0.f, 0.f, 0.f, 0.f);

    int head = cnt < 8 ? cnt : 8;
#pragma unroll
    for (int j = 0; j < 8; j++) {
        if (j < head) {
            const float* base = feat + (size_t)ridx[j] * ND + d0;
#pragma unroll
            for (int c = 0; c < NCHUNK; c++) {
                float4 v = *reinterpret_cast<const float4*>(base + c * 1024);
                acc[c].x += v.x; acc[c].y += v.y; acc[c].z += v.z; acc[c].w += v.w;
            }
        }
    }
    const int* row = g_ell_e + e * ESL;
    for (int j = 8; j < cnt; j++) {     // rare tail
        const float* base = feat + (size_t)row[j] * ND + d0;
#pragma unroll
        for (int c = 0; c < NCHUNK; c++) {
            float4 v = *reinterpret_cast<const float4*>(base + c * 1024);
            acc[c].x += v.x; acc[c].y += v.y; acc[c].z += v.z; acc[c].w += v.w;
        }
    }

    float* obase = out_edge + (size_t)e * ND + d0;
#pragma unroll
    for (int c = 0; c < NCHUNK; c++) {
        float4 a = acc[c];
        a.x *= b; a.y *= b; a.z *= b; a.w *= b;
        float4 lr;  // leaky relu (inverted later by k_node — no raw scratch needed)
        lr.x = a.x > 0.f ? a.x : NEG * a.x;
        lr.y = a.y > 0.f ? a.y : NEG * a.y;
        lr.z = a.z > 0.f ? a.z : NEG * a.z;
        lr.w = a.w > 0.f ? a.w : NEG * a.w;
        *reinterpret_cast<float4*>(obase + c * 1024) = lr;
    }
}

// ---------------- K3: node aggregation (4 nodes per block) ----------------
// grid: NN/NPB, block: 256 threads; metadata for all 4 nodes loaded up front
// reads leaky(edge_out) and inverts it (y>0 ? y : 100*y); err ~1e-7 << 1e-3
__global__ void __launch_bounds__(256) k_node(const float* __restrict__ edge_lr,
                                              const float* __restrict__ bias,
                                              float* __restrict__ out_node) {
    int nbase = blockIdx.x * NPB;
    int d0 = threadIdx.x * 4;
    const float inv = 1.0f / NEG;

    // batched metadata loads: 12 independent LDGs
    int   cnts[NPB];
    float dvs[NPB];
    int4  rows[NPB];
#pragma unroll
    for (int u = 0; u < NPB; u++) {
        int n = nbase + u;
        int c = g_ncur[n];
        cnts[u] = c < NSL ? c : NSL;
        float ds = g_D[n];
        dvs[u] = (ds == 0.f) ? 0.f : 1.f / ds;
        rows[u] = *reinterpret_cast<const int4*>(g_ell_n + n * NSL);  // first 4 ids
    }

    float4 bb[NCHUNK];
#pragma unroll
    for (int c = 0; c < NCHUNK; c++)
        bb[c] = *reinterpret_cast<const float4*>(bias + d0 + c * 1024);

#pragma unroll
    for (int u = 0; u < NPB; u++) {
        int n = nbase + u;
        int cnt = cnts[u];
        int ridx[4] = {rows[u].x, rows[u].y, rows[u].z, rows[u].w};
        float4 acc[NCHUNK];
#pragma unroll
        for (int c = 0; c < NCHUNK; c++) acc[c] = make_float4(0.f, 0.f, 0.f, 0.f);

        int head = cnt < 4 ? cnt : 4;
#pragma unroll
        for (int j = 0; j < 4; j++) {
            if (j < head) {
                const float* base = edge_lr + (size_t)ridx[j] * ND + d0;
#pragma unroll
                for (int c = 0; c < NCHUNK; c++) {
                    float4 v = *reinterpret_cast<const float4*>(base + c * 1024);
                    acc[c].x += v.x > 0.f ? v.x : inv * v.x;
                    acc[c].y += v.y > 0.f ? v.y : inv * v.y;
                    acc[c].z += v.z > 0.f ? v.z : inv * v.z;
                    acc[c].w += v.w > 0.f ? v.w : inv * v.w;
                }
            }
        }
        const int* row = g_ell_n + n * NSL;
        for (int j = 4; j < cnt; j++) {     // rare tail (P ~ 0.4%)
            const float* base = edge_lr + (size_t)row[j] * ND + d0;
#pragma unroll
            for (int c = 0; c < NCHUNK; c++) {
                float4 v = *reinterpret_cast<const float4*>(base + c * 1024);
                acc[c].x += v.x > 0.f ? v.x : inv * v.x;
                acc[c].y += v.y > 0.f ? v.y : inv * v.y;
                acc[c].z += v.z > 0.f ? v.z : inv * v.z;
                acc[c].w += v.w > 0.f ? v.w : inv * v.w;
            }
        }

        float dv = dvs[u];
        float* obase = out_node + (size_t)n * ND + d0;
#pragma unroll
        for (int c = 0; c < NCHUNK; c++) {
            float4 a = acc[c];
            a.x = a.x * dv + bb[c].x;
            a.y = a.y * dv + bb[c].y;
            a.z = a.z * dv + bb[c].z;
            a.w = a.w * dv + bb[c].w;
            float4 lr;
            lr.x = a.x > 0.f ? a.x : NEG * a.x;
            lr.y = a.y > 0.f ? a.y : NEG * a.y;
            lr.z = a.z > 0.f ? a.z : NEG * a.z;
            lr.w = a.w > 0.f ? a.w : NEG * a.w;
            // streaming store: out_node is never re-read; don't pollute L2
            __stcs(reinterpret_cast<float4*>(obase + c * 1024), lr);
        }
    }
}

// ---------------- launch ----------------
extern "C" void kernel_launch(void* const* d_in, const int* in_sizes, int n_in,
                              void* d_out, int out_size) {
    const float* feat = (const float*)d_in[0];   // features [5200,4096]
    const int*   hidx = (const int*)d_in[1];     // hyperedge_index [2,5200]
    const float* hw   = (const float*)d_in[3];   // hyperedge_weight [1000]
    const float* ew   = (const float*)d_in[6];   // EW_weight [5200]
    const float* bias = (const float*)d_in[7];   // bias [4096]

    const int* node_idx = hidx;        // row 0
    const int* edge_idx = hidx + NI;   // row 1

    float* out      = (float*)d_out;
    float* out_node = out;                       // [5200,4096]
    float* out_edge = out + (size_t)NN * ND;     // [1000,4096]

    k_zero<<<(NN + 511) / 512, 512>>>();
    k_build<<<(NI + 255) / 256, 256>>>(node_idx, edge_idx, hw, ew);
    k_edge<<<NH, 256>>>(feat, out_edge);
    k_node<<<NN / NPB, 256>>>(out_edge, bias, out_node);
}

// round 16
// speedup vs baseline: 1.3374x; 1.3374x over previous
#include <cuda_runtime.h>
#include <cuda_bf16.h>

#define NN 5200    // nodes
#define NI 5200    // incidences
#define NH 1000    // hyperedges
#define ND 4096    // feature dim
#define NEG 0.01f
#define ESL 48     // slots per edge bin (max degree seed-0 ~17, Poisson(5.2))
#define NSL 16     // slots per node bin (max degree ~9, Poisson(1))
#define NCHUNK 4   // 4 x 1024 floats = full 4096 row per block
#define NPB 4      // nodes per block in k_node

// ---------------- device scratch (no allocations; zero-init at load) ----------------
// Invariant: cursors/accumulators are ZERO at entry to k_build. True at load
// (static zero-init); thereafter each consumer kernel re-zeroes what it owns at
// the END of its block (after all reads), so every launch does identical work.
__device__ int   g_ncur[NN];          // node cursors -> final counts
__device__ int   g_ecur[NH];          // edge cursors -> final counts
__device__ float g_D[NN];
__device__ float g_B[NH];
__device__ int   g_ell_n[NN * NSL];   // per-node list of edge ids (padded)
__device__ int   g_ell_e[NH * ESL];   // per-edge list of node ids (padded)

// ---------------- K1: build ELL + degree sums via chip-wide global atomics ----------------
__global__ void k_build(const int* __restrict__ node_idx,
                        const int* __restrict__ edge_idx,
                        const float* __restrict__ hw,
                        const float* __restrict__ ew) {
    int i = blockIdx.x * blockDim.x + threadIdx.x;
    if (i >= NI) return;
    int n = node_idx[i];
    int e = edge_idx[i];
    int p = atomicAdd(&g_ecur[e], 1);
    if (p < ESL) g_ell_e[e * ESL + p] = n;   // fire-and-forget STG
    int q = atomicAdd(&g_ncur[n], 1);
    if (q < NSL) g_ell_n[n * NSL + q] = e;   // fire-and-forget STG
    atomicAdd(&g_D[n], hw[e]);               // REDG, no return
    atomicAdd(&g_B[e], ew[n]);               // REDG, no return
}

// ---------------- K2: edge aggregation (one block per hyperedge) ----------------
// grid: NH, block: 256 threads, 4 float4 chunks; first 8 ELL indices hoisted.
// Self-cleaning at END of block (no serialization of the hot path).
__global__ void __launch_bounds__(256) k_edge(const float* __restrict__ feat,
                                              float* __restrict__ out_edge) {
    int e  = blockIdx.x;
    int d0 = threadIdx.x * 4;
    int cnt = g_ecur[e]; cnt = cnt < ESL ? cnt : ESL;
    float bsum = g_B[e];
    float b = (bsum == 0.f) ? 0.f : 1.f / bsum;
    const int4* row4 = reinterpret_cast<const int4*>(g_ell_e + e * ESL);
    // hoist first 8 indices (covers ~92% of edges fully)
    int4 r0 = row4[0];
    int4 r1 = row4[1];
    int ridx[8] = {r0.x, r0.y, r0.z, r0.w, r1.x, r1.y, r1.z, r1.w};

    float4 acc[NCHUNK];
#pragma unroll
    for (int c = 0; c < NCHUNK; c++) acc[c] = make_float4(0.f, 0.f, 0.f, 0.f);

    int head = cnt < 8 ? cnt : 8;
#pragma unroll
    for (int j = 0; j < 8; j++) {
        if (j < head) {
            const float* base = feat + (size_t)ridx[j] * ND + d0;
#pragma unroll
            for (int c = 0; c < NCHUNK; c++) {
                float4 v = *reinterpret_cast<const float4*>(base + c * 1024);
                acc[c].x += v.x; acc[c].y += v.y; acc[c].z += v.z; acc[c].w += v.w;
            }
        }
    }
    const int* row = g_ell_e + e * ESL;
    for (int j = 8; j < cnt; j++) {     // rare tail
        const float* base = feat + (size_t)row[j] * ND + d0;
#pragma unroll
        for (int c = 0; c < NCHUNK; c++) {
            float4 v = *reinterpret_cast<const float4*>(base + c * 1024);
            acc[c].x += v.x; acc[c].y += v.y; acc[c].z += v.z; acc[c].w += v.w;
        }
    }

    float* obase = out_edge + (size_t)e * ND + d0;
#pragma unroll
    for (int c = 0; c < NCHUNK; c++) {
        float4 a = acc[c];
        a.x *= b; a.y *= b; a.z *= b; a.w *= b;
        float4 lr;  // leaky relu (inverted later by k_node — no raw scratch needed)
        lr.x = a.x > 0.f ? a.x : NEG * a.x;
        lr.y = a.y > 0.f ? a.y : NEG * a.y;
        lr.z = a.z > 0.f ? a.z : NEG * a.z;
        lr.w = a.w > 0.f ? a.w : NEG * a.w;
        *reinterpret_cast<float4*>(obase + c * 1024) = lr;
    }

    // ---- end-of-block cleanup for next replay (all reads happened at entry) ----
    __syncthreads();
    if (threadIdx.x == 0) { g_ecur[e] = 0; g_B[e] = 0.f; }
}

// ---------------- K3: node aggregation (4 nodes per block) ----------------
// grid: NN/NPB, block: 256 threads; metadata for all 4 nodes loaded up front.
// Self-cleaning at END of block. Reads leaky(edge_out) and inverts it
// (y>0 ? y : 100*y); err ~1e-7 << 1e-3.
__global__ void __launch_bounds__(256) k_node(const float* __restrict__ edge_lr,
                                              const float* __restrict__ bias,
                                              float* __restrict__ out_node) {
    int nbase = blockIdx.x * NPB;
    int d0 = threadIdx.x * 4;
    const float inv = 1.0f / NEG;

    // batched metadata loads: 12 independent LDGs
    int   cnts[NPB];
    float dvs[NPB];
    int4  rows[NPB];
#pragma unroll
    for (int u = 0; u < NPB; u++) {
        int n = nbase + u;
        int c = g_ncur[n];
        cnts[u] = c < NSL ? c : NSL;
        float ds = g_D[n];
        dvs[u] = (ds == 0.f) ? 0.f : 1.f / ds;
        rows[u] = *reinterpret_cast<const int4*>(g_ell_n + n * NSL);  // first 4 ids
    }

    float4 bb[NCHUNK];
#pragma unroll
    for (int c = 0; c < NCHUNK; c++)
        bb[c] = *reinterpret_cast<const float4*>(bias + d0 + c * 1024);

#pragma unroll
    for (int u = 0; u < NPB; u++) {
        int n = nbase + u;
        int cnt = cnts[u];
        int ridx[4] = {rows[u].x, rows[u].y, rows[u].z, rows[u].w};
        float4 acc[NCHUNK];
#pragma unroll
        for (int c = 0; c < NCHUNK; c++) acc[c] = make_float4(0.f, 0.f, 0.f, 0.f);

        int head = cnt < 4 ? cnt : 4;
#pragma unroll
        for (int j = 0; j < 4; j++) {
            if (j < head) {
                const float* base = edge_lr + (size_t)ridx[j] * ND + d0;
#pragma unroll
                for (int c = 0; c < NCHUNK; c++) {
                    float4 v = *reinterpret_cast<const float4*>(base + c * 1024);
                    acc[c].x += v.x > 0.f ? v.x : inv * v.x;
                    acc[c].y += v.y > 0.f ? v.y : inv * v.y;
                    acc[c].z += v.z > 0.f ? v.z : inv * v.z;
                    acc[c].w += v.w > 0.f ? v.w : inv * v.w;
                }
            }
        }
        const int* row = g_ell_n + n * NSL;
        for (int j = 4; j < cnt; j++) {     // rare tail (P ~ 0.4%)
            const float* base = edge_lr + (size_t)row[j] * ND + d0;
#pragma unroll
            for (int c = 0; c < NCHUNK; c++) {
                float4 v = *reinterpret_cast<const float4*>(base + c * 1024);
                acc[c].x += v.x > 0.f ? v.x : inv * v.x;
                acc[c].y += v.y > 0.f ? v.y : inv * v.y;
                acc[c].z += v.z > 0.f ? v.z : inv * v.z;
                acc[c].w += v.w > 0.f ? v.w : inv * v.w;
            }
        }

        float dv = dvs[u];
        float* obase = out_node + (size_t)n * ND + d0;
#pragma unroll
        for (int c = 0; c < NCHUNK; c++) {
            float4 a = acc[c];
            a.x = a.x * dv + bb[c].x;
            a.y = a.y * dv + bb[c].y;
            a.z = a.z * dv + bb[c].z;
            a.w = a.w * dv + bb[c].w;
            float4 lr;
            lr.x = a.x > 0.f ? a.x : NEG * a.x;
            lr.y = a.y > 0.f ? a.y : NEG * a.y;
            lr.z = a.z > 0.f ? a.z : NEG * a.z;
            lr.w = a.w > 0.f ? a.w : NEG * a.w;
            // streaming store: out_node is never re-read; don't pollute L2
            __stcs(reinterpret_cast<float4*>(obase + c * 1024), lr);
        }
    }

    // ---- end-of-block cleanup for next replay (all reads happened at entry) ----
    __syncthreads();
    if (threadIdx.x < NPB) {
        g_ncur[nbase + threadIdx.x] = 0;
        g_D[nbase + threadIdx.x]   = 0.f;
    }
}

// ---------------- launch ----------------
extern "C" void kernel_launch(void* const* d_in, const int* in_sizes, int n_in,
                              void* d_out, int out_size) {
    const float* feat = (const float*)d_in[0];   // features [5200,4096]
    const int*   hidx = (const int*)d_in[1];     // hyperedge_index [2,5200]
    const float* hw   = (const float*)d_in[3];   // hyperedge_weight [1000]
    const float* ew   = (const float*)d_in[6];   // EW_weight [5200]
    const float* bias = (const float*)d_in[7];   // bias [4096]

    const int* node_idx = hidx;        // row 0
    const int* edge_idx = hidx + NI;   // row 1

    float* out      = (float*)d_out;
    float* out_node = out;                       // [5200,4096]
    float* out_edge = out + (size_t)NN * ND;     // [1000,4096]

    k_build<<<(NI + 255) / 256, 256>>>(node_idx, edge_idx, hw, ew);
    k_edge<<<NH, 256>>>(feat, out_edge);
    k_node<<<NN / NPB, 256>>>(out_edge, bias, out_node);
}